// round 1
// baseline (speedup 1.0000x reference)
#include <cuda_runtime.h>
#include <cstddef>

// Problem constants
constexpr int B_  = 4;
constexpr int S_  = 2048;
constexpr int H_  = 1024;
constexpr int NH_ = 16;
constexpr int HD_ = 64;
constexpr int M_  = B_ * S_;   // 8192 rows

// Scratch (device globals — no allocation allowed)
__device__ float g_q[(size_t)B_ * NH_ * S_ * HD_];   // [B*NH, S, HD]
__device__ float g_k[(size_t)B_ * NH_ * S_ * HD_];
__device__ float g_v[(size_t)B_ * NH_ * S_ * HD_];
__device__ float g_att[(size_t)M_ * H_];             // [B*S, H]

// ----------------------------------------------------------------------------
// SGEMM: C = A @ W^T + bias.  A: [M,K] row-major, W: [N,K] row-major.
// MODE 0: C stored [M,N] row-major.
// MODE 1: C scattered into [B*NH, S, HD] (head-split for Q/K/V).
// Tile: 128x128x16, 256 threads, 8x8 per thread.
// ----------------------------------------------------------------------------
constexpr int BM = 128, BN = 128, BK = 16, TM = 8, TN = 8;

template <int MODE>
__global__ __launch_bounds__(256)
void gemm_bias(const float* __restrict__ A, const float* __restrict__ W,
               const float* __restrict__ bias, float* __restrict__ C,
               int N, int K)
{
    __shared__ float As[BK][BM];
    __shared__ float Bs[BK][BN];

    const int tid = threadIdx.x;
    const int m0 = blockIdx.y * BM;
    const int n0 = blockIdx.x * BN;
    const int trow = (tid >> 4) * TM;   // 0..120
    const int tcol = (tid & 15) * TN;   // 0..120

    float acc[TM][TN];
    #pragma unroll
    for (int i = 0; i < TM; i++)
        #pragma unroll
        for (int j = 0; j < TN; j++) acc[i][j] = 0.f;

    for (int k0 = 0; k0 < K; k0 += BK) {
        // Load A tile (128x16) and W tile (128x16), stored transposed in smem.
        #pragma unroll
        for (int t = 0; t < 2; t++) {
            int idx = tid + t * 256;            // 0..511
            int row = idx >> 2;                 // 0..127
            int c4  = idx & 3;                  // 0..3
            float4 va = *reinterpret_cast<const float4*>(
                &A[(size_t)(m0 + row) * K + k0 + c4 * 4]);
            As[c4 * 4 + 0][row] = va.x;
            As[c4 * 4 + 1][row] = va.y;
            As[c4 * 4 + 2][row] = va.z;
            As[c4 * 4 + 3][row] = va.w;
            float4 vb = *reinterpret_cast<const float4*>(
                &W[(size_t)(n0 + row) * K + k0 + c4 * 4]);
            Bs[c4 * 4 + 0][row] = vb.x;
            Bs[c4 * 4 + 1][row] = vb.y;
            Bs[c4 * 4 + 2][row] = vb.z;
            Bs[c4 * 4 + 3][row] = vb.w;
        }
        __syncthreads();

        #pragma unroll
        for (int k = 0; k < BK; k++) {
            float ar[TM], br[TN];
            #pragma unroll
            for (int i = 0; i < TM; i += 4)
                *reinterpret_cast<float4*>(&ar[i]) =
                    *reinterpret_cast<const float4*>(&As[k][trow + i]);
            #pragma unroll
            for (int j = 0; j < TN; j += 4)
                *reinterpret_cast<float4*>(&br[j]) =
                    *reinterpret_cast<const float4*>(&Bs[k][tcol + j]);
            #pragma unroll
            for (int i = 0; i < TM; i++)
                #pragma unroll
                for (int j = 0; j < TN; j++)
                    acc[i][j] = fmaf(ar[i], br[j], acc[i][j]);
        }
        __syncthreads();
    }

    // Epilogue: bias + store
    #pragma unroll
    for (int i = 0; i < TM; i++) {
        int m = m0 + trow + i;
        #pragma unroll
        for (int j = 0; j < TN; j++) {
            int n = n0 + tcol + j;
            float val = acc[i][j] + __ldg(&bias[n]);
            if (MODE == 0) {
                C[(size_t)m * N + n] = val;
            } else {
                int b  = m / S_, s  = m % S_;
                int h  = n / HD_, hd = n % HD_;
                C[(((size_t)(b * NH_ + h)) * S_ + s) * HD_ + hd] = val;
            }
        }
    }
}

// ----------------------------------------------------------------------------
// Flash attention (causal), fp32.
// Grid: (S/64, B*NH). 256 threads, 16x16 thread grid, 4x4 microtile.
// Smem: Qs[64][64], Kt[64][65] (d-major), Vs[64][64], Pt[64][65] (key-major).
// ----------------------------------------------------------------------------
constexpr int BQ = 64, BKV = 64;
constexpr int ATTN_SMEM_FLOATS = 64 * 64 + 64 * 65 + 64 * 64 + 64 * 65;

__global__ __launch_bounds__(256)
void attn_kernel(const float* __restrict__ Q, const float* __restrict__ K,
                 const float* __restrict__ V, float* __restrict__ Oa)
{
    extern __shared__ float sm[];
    float* Qs = sm;                    // [64][64]
    float* Kt = Qs + 64 * 64;          // [64(d)][65]
    float* Vs = Kt + 64 * 65;          // [64][64]
    float* Pt = Vs + 64 * 64;          // [64(c)][65]

    const int tid = threadIdx.x;
    const int qt = blockIdx.x;
    const int bh = blockIdx.y;
    const int q0 = qt * BQ;

    const float* Qb = Q + (size_t)bh * S_ * HD_;
    const float* Kb = K + (size_t)bh * S_ * HD_;
    const float* Vb = V + (size_t)bh * S_ * HD_;

    const int tx = tid & 15, ty = tid >> 4;
    const int trow = ty * 4;  // query rows
    const int tcol = tx * 4;  // key cols (phase 1) / hd cols (phase 2)

    // Load Q tile [64][64], coalesced, no transpose.
    #pragma unroll
    for (int t = 0; t < 4; t++) {
        int idx = tid + t * 256;
        int r = idx >> 4, d4 = idx & 15;
        *reinterpret_cast<float4*>(&Qs[r * 64 + d4 * 4]) =
            *reinterpret_cast<const float4*>(&Qb[(size_t)(q0 + r) * HD_ + d4 * 4]);
    }

    float m_i[4], l_i[4], o[4][4];
    #pragma unroll
    for (int i = 0; i < 4; i++) {
        m_i[i] = -1e30f; l_i[i] = 0.f;
        #pragma unroll
        for (int j = 0; j < 4; j++) o[i][j] = 0.f;
    }

    const float scale = 0.125f;  // 1/sqrt(64)

    for (int kt = 0; kt <= qt; kt++) {
        const int k0 = kt * BKV;
        __syncthreads();   // previous PV done (also covers Q load on iter 0)

        // Load K tile transposed (Kt[d][c], padded 65) and V tile natural.
        #pragma unroll
        for (int t = 0; t < 4; t++) {
            int idx = tid + t * 256;
            int c = idx >> 4, d4 = idx & 15;
            float4 kv = *reinterpret_cast<const float4*>(
                &Kb[(size_t)(k0 + c) * HD_ + d4 * 4]);
            Kt[(d4 * 4 + 0) * 65 + c] = kv.x;
            Kt[(d4 * 4 + 1) * 65 + c] = kv.y;
            Kt[(d4 * 4 + 2) * 65 + c] = kv.z;
            Kt[(d4 * 4 + 3) * 65 + c] = kv.w;
            *reinterpret_cast<float4*>(&Vs[c * 64 + d4 * 4]) =
                *reinterpret_cast<const float4*>(&Vb[(size_t)(k0 + c) * HD_ + d4 * 4]);
        }
        __syncthreads();

        // S = Q @ K^T  (64x64, 4x4 per thread)
        float s[4][4];
        #pragma unroll
        for (int i = 0; i < 4; i++)
            #pragma unroll
            for (int j = 0; j < 4; j++) s[i][j] = 0.f;

        #pragma unroll 8
        for (int d = 0; d < HD_; d++) {
            float qr[4], kr[4];
            #pragma unroll
            for (int i = 0; i < 4; i++) qr[i] = Qs[(trow + i) * 64 + d];
            #pragma unroll
            for (int j = 0; j < 4; j++) kr[j] = Kt[d * 65 + tcol + j];
            #pragma unroll
            for (int i = 0; i < 4; i++)
                #pragma unroll
                for (int j = 0; j < 4; j++)
                    s[i][j] = fmaf(qr[i], kr[j], s[i][j]);
        }

        // scale + causal mask (only diagonal tile needs masking)
        const bool diag = (kt == qt);
        #pragma unroll
        for (int i = 0; i < 4; i++)
            #pragma unroll
            for (int j = 0; j < 4; j++) {
                float v = s[i][j] * scale;
                if (diag && (tcol + j > trow + i)) v = -1e30f;
                s[i][j] = v;
            }

        // Online softmax update per row
        #pragma unroll
        for (int i = 0; i < 4; i++) {
            float mx = fmaxf(fmaxf(s[i][0], s[i][1]), fmaxf(s[i][2], s[i][3]));
            mx = fmaxf(mx, __shfl_xor_sync(0xffffffffu, mx, 1));
            mx = fmaxf(mx, __shfl_xor_sync(0xffffffffu, mx, 2));
            mx = fmaxf(mx, __shfl_xor_sync(0xffffffffu, mx, 4));
            mx = fmaxf(mx, __shfl_xor_sync(0xffffffffu, mx, 8));
            float nm   = fmaxf(m_i[i], mx);
            float corr = __expf(m_i[i] - nm);
            float rs = 0.f;
            #pragma unroll
            for (int j = 0; j < 4; j++) {
                float p = __expf(s[i][j] - nm);
                s[i][j] = p;
                rs += p;
            }
            rs += __shfl_xor_sync(0xffffffffu, rs, 1);
            rs += __shfl_xor_sync(0xffffffffu, rs, 2);
            rs += __shfl_xor_sync(0xffffffffu, rs, 4);
            rs += __shfl_xor_sync(0xffffffffu, rs, 8);
            l_i[i] = l_i[i] * corr + rs;
            m_i[i] = nm;
            #pragma unroll
            for (int j = 0; j < 4; j++) o[i][j] *= corr;
        }

        // Stage P transposed: Pt[c][r]
        #pragma unroll
        for (int j = 0; j < 4; j++)
            #pragma unroll
            for (int i = 0; i < 4; i++)
                Pt[(tcol + j) * 65 + trow + i] = s[i][j];
        __syncthreads();

        // O += P @ V  (rows=query, cols=hd)
        #pragma unroll 8
        for (int c = 0; c < BKV; c++) {
            float pr[4];
            #pragma unroll
            for (int i = 0; i < 4; i++) pr[i] = Pt[c * 65 + trow + i];
            float4 vv = *reinterpret_cast<const float4*>(&Vs[c * 64 + tcol]);
            float vr[4] = {vv.x, vv.y, vv.z, vv.w};
            #pragma unroll
            for (int i = 0; i < 4; i++)
                #pragma unroll
                for (int j = 0; j < 4; j++)
                    o[i][j] = fmaf(pr[i], vr[j], o[i][j]);
        }
    }

    // Epilogue: normalize and write to [B, S, H] layout for the output proj.
    const int b = bh / NH_, h = bh % NH_;
    #pragma unroll
    for (int i = 0; i < 4; i++) {
        float inv = 1.f / l_i[i];
        int srow = q0 + trow + i;
        float4 ov;
        ov.x = o[i][0] * inv;
        ov.y = o[i][1] * inv;
        ov.z = o[i][2] * inv;
        ov.w = o[i][3] * inv;
        *reinterpret_cast<float4*>(
            &Oa[((size_t)(b * S_ + srow)) * H_ + h * HD_ + tcol]) = ov;
    }
}

// ----------------------------------------------------------------------------
// Launch
// ----------------------------------------------------------------------------
extern "C" void kernel_launch(void* const* d_in, const int* in_sizes, int n_in,
                              void* d_out, int out_size)
{
    const float* x  = (const float*)d_in[0];
    const float* Wq = (const float*)d_in[1];
    const float* bq = (const float*)d_in[2];
    const float* Wk = (const float*)d_in[3];
    const float* bk = (const float*)d_in[4];
    const float* Wv = (const float*)d_in[5];
    const float* bv = (const float*)d_in[6];
    const float* Wo = (const float*)d_in[7];
    const float* bo = (const float*)d_in[8];
    float* out = (float*)d_out;

    float *q, *k, *v, *att;
    cudaGetSymbolAddress((void**)&q,   g_q);
    cudaGetSymbolAddress((void**)&k,   g_k);
    cudaGetSymbolAddress((void**)&v,   g_v);
    cudaGetSymbolAddress((void**)&att, g_att);

    const size_t attn_smem = (size_t)ATTN_SMEM_FLOATS * sizeof(float);
    cudaFuncSetAttribute(attn_kernel,
                         cudaFuncAttributeMaxDynamicSharedMemorySize,
                         (int)attn_smem);

    dim3 gemm_grid(H_ / BN, M_ / BM);  // (8, 64)
    dim3 gemm_block(256);

    gemm_bias<1><<<gemm_grid, gemm_block>>>(x, Wq, bq, q, H_, H_);
    gemm_bias<1><<<gemm_grid, gemm_block>>>(x, Wk, bk, k, H_, H_);
    gemm_bias<1><<<gemm_grid, gemm_block>>>(x, Wv, bv, v, H_, H_);

    dim3 attn_grid(S_ / BQ, B_ * NH_);  // (32, 64)
    attn_kernel<<<attn_grid, 256, attn_smem>>>(q, k, v, att);

    gemm_bias<0><<<gemm_grid, gemm_block>>>(att, Wo, bo, out, H_, H_);
}

// round 3
// speedup vs baseline: 1.6432x; 1.6432x over previous
#include <cuda_runtime.h>
#include <cuda_bf16.h>
#include <cstdint>
#include <cstddef>

// Problem constants
constexpr int B_  = 4;
constexpr int S_  = 2048;
constexpr int H_  = 1024;
constexpr int NH_ = 16;
constexpr int HD_ = 64;
constexpr int M_  = B_ * S_;   // 8192 rows

// ---------------------------------------------------------------------------
// Scratch (device globals — no allocation allowed)
// ---------------------------------------------------------------------------
__device__ float g_q[(size_t)B_ * NH_ * S_ * HD_];   // [B*NH, S, HD]
__device__ float g_k[(size_t)B_ * NH_ * S_ * HD_];
__device__ float g_v[(size_t)B_ * NH_ * S_ * HD_];
__device__ float g_att[(size_t)M_ * H_];             // [B*S, H]

__device__ __nv_bfloat16 g_xhi[(size_t)M_ * H_];
__device__ __nv_bfloat16 g_xlo[(size_t)M_ * H_];
__device__ __nv_bfloat16 g_ahi[(size_t)M_ * H_];
__device__ __nv_bfloat16 g_alo[(size_t)M_ * H_];
__device__ __nv_bfloat16 g_whi[4 * (size_t)H_ * H_];
__device__ __nv_bfloat16 g_wlo[4 * (size_t)H_ * H_];

// ---------------------------------------------------------------------------
// Helpers (base sm_103 only: mma.sync / ldmatrix / cp.async — NO tcgen05)
// ---------------------------------------------------------------------------
__device__ __forceinline__ uint32_t smem_u32(const void* p) {
    uint32_t a;
    asm("{ .reg .u64 t; cvta.to.shared.u64 t, %1; cvt.u32.u64 %0, t; }"
        : "=r"(a) : "l"(p));
    return a;
}

__device__ __forceinline__ void cp_async16(uint32_t dst, const void* src) {
    asm volatile("cp.async.cg.shared.global [%0], [%1], 16;"
                 :: "r"(dst), "l"(src) : "memory");
}
#define CP_COMMIT() asm volatile("cp.async.commit_group;" ::: "memory")
#define CP_WAIT(n)  asm volatile("cp.async.wait_group %0;" :: "n"(n) : "memory")

__device__ __forceinline__ void ldmatrix_x4(uint32_t* r, uint32_t addr) {
    asm volatile("ldmatrix.sync.aligned.m8n8.x4.shared.b16 {%0,%1,%2,%3}, [%4];"
                 : "=r"(r[0]), "=r"(r[1]), "=r"(r[2]), "=r"(r[3]) : "r"(addr));
}
__device__ __forceinline__ void ldmatrix_x2(uint32_t* r, uint32_t addr) {
    asm volatile("ldmatrix.sync.aligned.m8n8.x2.shared.b16 {%0,%1}, [%2];"
                 : "=r"(r[0]), "=r"(r[1]) : "r"(addr));
}
__device__ __forceinline__ void mma_bf16(float* c, const uint32_t* a,
                                         const uint32_t* b) {
    asm volatile(
        "mma.sync.aligned.m16n8k16.row.col.f32.bf16.bf16.f32 "
        "{%0,%1,%2,%3}, {%4,%5,%6,%7}, {%8,%9}, {%0,%1,%2,%3};"
        : "+f"(c[0]), "+f"(c[1]), "+f"(c[2]), "+f"(c[3])
        : "r"(a[0]), "r"(a[1]), "r"(a[2]), "r"(a[3]), "r"(b[0]), "r"(b[1]));
}

// ---------------------------------------------------------------------------
// Split fp32 -> (bf16 hi, bf16 lo) — vectorized by 4
// ---------------------------------------------------------------------------
__global__ __launch_bounds__(256)
void split_kernel(const float* __restrict__ src,
                  __nv_bfloat16* __restrict__ hi,
                  __nv_bfloat16* __restrict__ lo, int n4)
{
    int i = blockIdx.x * blockDim.x + threadIdx.x;
    if (i >= n4) return;
    float4 v = reinterpret_cast<const float4*>(src)[i];
    __nv_bfloat16 h0 = __float2bfloat16(v.x);
    __nv_bfloat16 h1 = __float2bfloat16(v.y);
    __nv_bfloat16 h2 = __float2bfloat16(v.z);
    __nv_bfloat16 h3 = __float2bfloat16(v.w);
    __nv_bfloat16 l0 = __float2bfloat16(v.x - __bfloat162float(h0));
    __nv_bfloat16 l1 = __float2bfloat16(v.y - __bfloat162float(h1));
    __nv_bfloat16 l2 = __float2bfloat16(v.z - __bfloat162float(h2));
    __nv_bfloat16 l3 = __float2bfloat16(v.w - __bfloat162float(h3));
    __nv_bfloat162 hp0{h0, h1}, hp1{h2, h3}, lp0{l0, l1}, lp1{l2, l3};
    uint2 hu, lu;
    hu.x = *reinterpret_cast<uint32_t*>(&hp0);
    hu.y = *reinterpret_cast<uint32_t*>(&hp1);
    lu.x = *reinterpret_cast<uint32_t*>(&lp0);
    lu.y = *reinterpret_cast<uint32_t*>(&lp1);
    reinterpret_cast<uint2*>(hi)[i] = hu;
    reinterpret_cast<uint2*>(lo)[i] = lu;
}

// ---------------------------------------------------------------------------
// HMMA bf16x3 GEMM:  C = A @ W^T + bias
// A = Ahi+Alo [M,K] row-major bf16; W = Whi+Wlo [N,K] row-major bf16.
// 3 accumulation passes: hi*hi, hi*lo, lo*hi (fp32 accumulators throughout).
// CTA tile 128x128, K-chunk 32. 8 warps, each 64x32 (4x4 of m16n8k16).
// cp.async double-buffered smem, padded rows (40 bf16 = 80B) for ldmatrix.
// MODE 0: C stored [M, H_]. MODE 1: head-split scatter to [B*NH, S, HD].
// ---------------------------------------------------------------------------
constexpr int BKK   = 32;                    // bf16 K per chunk
constexpr int RPAD  = 40;                    // padded row length (elements)
constexpr int TILEB = 128 * RPAD * 2;        // 10240 B per tile
constexpr int BUFB  = 2 * TILEB;             // A+B per buffer
constexpr int GEMM_SMEM = 2 * BUFB;          // 40960 B

template <int MODE>
__global__ __launch_bounds__(256)
void gemm_mma(const __nv_bfloat16* __restrict__ Ahi,
              const __nv_bfloat16* __restrict__ Alo,
              const __nv_bfloat16* __restrict__ Whi,
              const __nv_bfloat16* __restrict__ Wlo,
              const float* __restrict__ bias, float* __restrict__ C)
{
    extern __shared__ char smem[];
    const uint32_t sb = smem_u32(smem);
    const int tid  = threadIdx.x;
    const int wid  = tid >> 5;
    const int lane = tid & 31;
    const int m0 = blockIdx.y * 128;
    const int n0 = blockIdx.x * 128;
    const int wm = (wid & 1) * 64;    // warp row base in tile
    const int wn = (wid >> 1) * 32;   // warp col base in tile

    float acc[4][4][4];
    #pragma unroll
    for (int mi = 0; mi < 4; mi++)
        #pragma unroll
        for (int ni = 0; ni < 4; ni++)
            #pragma unroll
            for (int r = 0; r < 4; r++) acc[mi][ni][r] = 0.f;

    const __nv_bfloat16* APASS[3] = {Ahi, Ahi, Alo};
    const __nv_bfloat16* BPASS[3] = {Whi, Wlo, Whi};
    constexpr int KCH = H_ / BKK;   // 32
    constexpr int NCH = 3 * KCH;    // 96

    auto issue_load = [&](int c) {
        const int pass = c / KCH, kc = c % KCH;
        const __nv_bfloat16* Ap = APASS[pass] + (size_t)m0 * H_ + kc * BKK;
        const __nv_bfloat16* Bp = BPASS[pass] + (size_t)n0 * H_ + kc * BKK;
        const uint32_t a_s = sb + (c & 1) * BUFB;
        const uint32_t b_s = a_s + TILEB;
        #pragma unroll
        for (int t = 0; t < 2; t++) {
            int u = tid + t * 256;        // 0..511
            int row = u >> 2, seg = u & 3;
            cp_async16(a_s + (row * RPAD + seg * 8) * 2,
                       Ap + (size_t)row * H_ + seg * 8);
            cp_async16(b_s + (row * RPAD + seg * 8) * 2,
                       Bp + (size_t)row * H_ + seg * 8);
        }
        CP_COMMIT();
    };

    issue_load(0);

    for (int c = 0; c < NCH; c++) {
        if (c + 1 < NCH) { issue_load(c + 1); CP_WAIT(1); }
        else             { CP_WAIT(0); }
        __syncthreads();

        const uint32_t a_s = sb + (c & 1) * BUFB;
        const uint32_t b_s = a_s + TILEB;

        #pragma unroll
        for (int ks = 0; ks < 2; ks++) {
            uint32_t a_frag[4][4], b_frag[4][2];
            #pragma unroll
            for (int mi = 0; mi < 4; mi++) {
                uint32_t addr = a_s +
                    ((wm + mi * 16 + (lane & 15)) * RPAD + ks * 16 + (lane >> 4) * 8) * 2;
                ldmatrix_x4(a_frag[mi], addr);
            }
            #pragma unroll
            for (int ni = 0; ni < 4; ni++) {
                int l = lane & 15;
                uint32_t addr = b_s +
                    ((wn + ni * 8 + (l & 7)) * RPAD + ks * 16 + (l >> 3) * 8) * 2;
                ldmatrix_x2(b_frag[ni], addr);
            }
            #pragma unroll
            for (int mi = 0; mi < 4; mi++)
                #pragma unroll
                for (int ni = 0; ni < 4; ni++)
                    mma_bf16(acc[mi][ni], a_frag[mi], b_frag[ni]);
        }
        __syncthreads();
    }

    // Epilogue: bias + store (2-wide fp32 pairs per fragment row)
    const int frow = lane >> 2;            // 0..7
    const int fcol = (lane & 3) * 2;       // 0,2,4,6
    #pragma unroll
    for (int mi = 0; mi < 4; mi++) {
        #pragma unroll
        for (int ni = 0; ni < 4; ni++) {
            const int n = n0 + wn + ni * 8 + fcol;
            const float b0 = __ldg(&bias[n]);
            const float b1 = __ldg(&bias[n + 1]);
            #pragma unroll
            for (int half = 0; half < 2; half++) {
                const int m = m0 + wm + mi * 16 + frow + half * 8;
                float2 val;
                val.x = acc[mi][ni][half * 2 + 0] + b0;
                val.y = acc[mi][ni][half * 2 + 1] + b1;
                if (MODE == 0) {
                    *reinterpret_cast<float2*>(&C[(size_t)m * H_ + n]) = val;
                } else {
                    const int b = m >> 11, s = m & 2047;
                    const int h = n >> 6, hd = n & 63;
                    *reinterpret_cast<float2*>(
                        &C[(((size_t)(b * NH_ + h)) * S_ + s) * HD_ + hd]) = val;
                }
            }
        }
    }
}

// ---------------------------------------------------------------------------
// Flash attention (causal), fp32 — unchanged (correct, fma-bound).
// ---------------------------------------------------------------------------
constexpr int BQ = 64, BKV = 64;
constexpr int ATTN_SMEM_FLOATS = 64 * 64 + 64 * 65 + 64 * 64 + 64 * 65;

__global__ __launch_bounds__(256)
void attn_kernel(const float* __restrict__ Q, const float* __restrict__ K,
                 const float* __restrict__ V, float* __restrict__ Oa)
{
    extern __shared__ float sm[];
    float* Qs = sm;                    // [64][64]
    float* Kt = Qs + 64 * 64;          // [64(d)][65]
    float* Vs = Kt + 64 * 65;          // [64][64]
    float* Pt = Vs + 64 * 64;          // [64(c)][65]

    const int tid = threadIdx.x;
    const int qt = blockIdx.x;
    const int bh = blockIdx.y;
    const int q0 = qt * BQ;

    const float* Qb = Q + (size_t)bh * S_ * HD_;
    const float* Kb = K + (size_t)bh * S_ * HD_;
    const float* Vb = V + (size_t)bh * S_ * HD_;

    const int tx = tid & 15, ty = tid >> 4;
    const int trow = ty * 4;
    const int tcol = tx * 4;

    #pragma unroll
    for (int t = 0; t < 4; t++) {
        int idx = tid + t * 256;
        int r = idx >> 4, d4 = idx & 15;
        *reinterpret_cast<float4*>(&Qs[r * 64 + d4 * 4]) =
            *reinterpret_cast<const float4*>(&Qb[(size_t)(q0 + r) * HD_ + d4 * 4]);
    }

    float m_i[4], l_i[4], o[4][4];
    #pragma unroll
    for (int i = 0; i < 4; i++) {
        m_i[i] = -1e30f; l_i[i] = 0.f;
        #pragma unroll
        for (int j = 0; j < 4; j++) o[i][j] = 0.f;
    }

    const float scale = 0.125f;

    for (int kt = 0; kt <= qt; kt++) {
        const int k0 = kt * BKV;
        __syncthreads();

        #pragma unroll
        for (int t = 0; t < 4; t++) {
            int idx = tid + t * 256;
            int c = idx >> 4, d4 = idx & 15;
            float4 kv = *reinterpret_cast<const float4*>(
                &Kb[(size_t)(k0 + c) * HD_ + d4 * 4]);
            Kt[(d4 * 4 + 0) * 65 + c] = kv.x;
            Kt[(d4 * 4 + 1) * 65 + c] = kv.y;
            Kt[(d4 * 4 + 2) * 65 + c] = kv.z;
            Kt[(d4 * 4 + 3) * 65 + c] = kv.w;
            *reinterpret_cast<float4*>(&Vs[c * 64 + d4 * 4]) =
                *reinterpret_cast<const float4*>(&Vb[(size_t)(k0 + c) * HD_ + d4 * 4]);
        }
        __syncthreads();

        float s[4][4];
        #pragma unroll
        for (int i = 0; i < 4; i++)
            #pragma unroll
            for (int j = 0; j < 4; j++) s[i][j] = 0.f;

        #pragma unroll 8
        for (int d = 0; d < HD_; d++) {
            float qr[4], kr[4];
            #pragma unroll
            for (int i = 0; i < 4; i++) qr[i] = Qs[(trow + i) * 64 + d];
            #pragma unroll
            for (int j = 0; j < 4; j++) kr[j] = Kt[d * 65 + tcol + j];
            #pragma unroll
            for (int i = 0; i < 4; i++)
                #pragma unroll
                for (int j = 0; j < 4; j++)
                    s[i][j] = fmaf(qr[i], kr[j], s[i][j]);
        }

        const bool diag = (kt == qt);
        #pragma unroll
        for (int i = 0; i < 4; i++)
            #pragma unroll
            for (int j = 0; j < 4; j++) {
                float v = s[i][j] * scale;
                if (diag && (tcol + j > trow + i)) v = -1e30f;
                s[i][j] = v;
            }

        #pragma unroll
        for (int i = 0; i < 4; i++) {
            float mx = fmaxf(fmaxf(s[i][0], s[i][1]), fmaxf(s[i][2], s[i][3]));
            mx = fmaxf(mx, __shfl_xor_sync(0xffffffffu, mx, 1));
            mx = fmaxf(mx, __shfl_xor_sync(0xffffffffu, mx, 2));
            mx = fmaxf(mx, __shfl_xor_sync(0xffffffffu, mx, 4));
            mx = fmaxf(mx, __shfl_xor_sync(0xffffffffu, mx, 8));
            float nm   = fmaxf(m_i[i], mx);
            float corr = __expf(m_i[i] - nm);
            float rs = 0.f;
            #pragma unroll
            for (int j = 0; j < 4; j++) {
                float p = __expf(s[i][j] - nm);
                s[i][j] = p;
                rs += p;
            }
            rs += __shfl_xor_sync(0xffffffffu, rs, 1);
            rs += __shfl_xor_sync(0xffffffffu, rs, 2);
            rs += __shfl_xor_sync(0xffffffffu, rs, 4);
            rs += __shfl_xor_sync(0xffffffffu, rs, 8);
            l_i[i] = l_i[i] * corr + rs;
            m_i[i] = nm;
            #pragma unroll
            for (int j = 0; j < 4; j++) o[i][j] *= corr;
        }

        #pragma unroll
        for (int j = 0; j < 4; j++)
            #pragma unroll
            for (int i = 0; i < 4; i++)
                Pt[(tcol + j) * 65 + trow + i] = s[i][j];
        __syncthreads();

        #pragma unroll 8
        for (int c = 0; c < BKV; c++) {
            float pr[4];
            #pragma unroll
            for (int i = 0; i < 4; i++) pr[i] = Pt[c * 65 + trow + i];
            float4 vv = *reinterpret_cast<const float4*>(&Vs[c * 64 + tcol]);
            float vr[4] = {vv.x, vv.y, vv.z, vv.w};
            #pragma unroll
            for (int i = 0; i < 4; i++)
                #pragma unroll
                for (int j = 0; j < 4; j++)
                    o[i][j] = fmaf(pr[i], vr[j], o[i][j]);
        }
    }

    const int b = bh / NH_, h = bh % NH_;
    #pragma unroll
    for (int i = 0; i < 4; i++) {
        float inv = 1.f / l_i[i];
        int srow = q0 + trow + i;
        float4 ov;
        ov.x = o[i][0] * inv;
        ov.y = o[i][1] * inv;
        ov.z = o[i][2] * inv;
        ov.w = o[i][3] * inv;
        *reinterpret_cast<float4*>(
            &Oa[((size_t)(b * S_ + srow)) * H_ + h * HD_ + tcol]) = ov;
    }
}

// ---------------------------------------------------------------------------
// Launch
// ---------------------------------------------------------------------------
extern "C" void kernel_launch(void* const* d_in, const int* in_sizes, int n_in,
                              void* d_out, int out_size)
{
    const float* x  = (const float*)d_in[0];
    const float* Wq = (const float*)d_in[1];
    const float* bq = (const float*)d_in[2];
    const float* Wk = (const float*)d_in[3];
    const float* bk = (const float*)d_in[4];
    const float* Wv = (const float*)d_in[5];
    const float* bv = (const float*)d_in[6];
    const float* Wo = (const float*)d_in[7];
    const float* bo = (const float*)d_in[8];
    float* out = (float*)d_out;

    float *q, *k, *v, *att;
    cudaGetSymbolAddress((void**)&q,   g_q);
    cudaGetSymbolAddress((void**)&k,   g_k);
    cudaGetSymbolAddress((void**)&v,   g_v);
    cudaGetSymbolAddress((void**)&att, g_att);
    __nv_bfloat16 *xhi, *xlo, *ahi, *alo, *whi, *wlo;
    cudaGetSymbolAddress((void**)&xhi, g_xhi);
    cudaGetSymbolAddress((void**)&xlo, g_xlo);
    cudaGetSymbolAddress((void**)&ahi, g_ahi);
    cudaGetSymbolAddress((void**)&alo, g_alo);
    cudaGetSymbolAddress((void**)&whi, g_whi);
    cudaGetSymbolAddress((void**)&wlo, g_wlo);

    const size_t attn_smem = (size_t)ATTN_SMEM_FLOATS * sizeof(float);
    cudaFuncSetAttribute(attn_kernel,
                         cudaFuncAttributeMaxDynamicSharedMemorySize, (int)attn_smem);
    cudaFuncSetAttribute(gemm_mma<0>,
                         cudaFuncAttributeMaxDynamicSharedMemorySize, GEMM_SMEM);
    cudaFuncSetAttribute(gemm_mma<1>,
                         cudaFuncAttributeMaxDynamicSharedMemorySize, GEMM_SMEM);

    const size_t WN = (size_t)H_ * H_;

    // Split inputs / weights to bf16 hi/lo pairs
    {
        int n4 = (M_ * H_) / 4;
        split_kernel<<<(n4 + 255) / 256, 256>>>(x, xhi, xlo, n4);
        int w4 = (H_ * H_) / 4;
        split_kernel<<<(w4 + 255) / 256, 256>>>(Wq, whi + 0 * WN, wlo + 0 * WN, w4);
        split_kernel<<<(w4 + 255) / 256, 256>>>(Wk, whi + 1 * WN, wlo + 1 * WN, w4);
        split_kernel<<<(w4 + 255) / 256, 256>>>(Wv, whi + 2 * WN, wlo + 2 * WN, w4);
        split_kernel<<<(w4 + 255) / 256, 256>>>(Wo, whi + 3 * WN, wlo + 3 * WN, w4);
    }

    dim3 ggrid(H_ / 128, M_ / 128);   // (8, 64)
    gemm_mma<1><<<ggrid, 256, GEMM_SMEM>>>(xhi, xlo, whi + 0 * WN, wlo + 0 * WN, bq, q);
    gemm_mma<1><<<ggrid, 256, GEMM_SMEM>>>(xhi, xlo, whi + 1 * WN, wlo + 1 * WN, bk, k);
    gemm_mma<1><<<ggrid, 256, GEMM_SMEM>>>(xhi, xlo, whi + 2 * WN, wlo + 2 * WN, bv, v);

    dim3 attn_grid(S_ / BQ, B_ * NH_);  // (32, 64)
    attn_kernel<<<attn_grid, 256, attn_smem>>>(q, k, v, att);

    {
        int n4 = (M_ * H_) / 4;
        split_kernel<<<(n4 + 255) / 256, 256>>>(att, ahi, alo, n4);
    }
    gemm_mma<0><<<ggrid, 256, GEMM_SMEM>>>(ahi, alo, whi + 3 * WN, wlo + 3 * WN, bo, out);
}

// round 4
// speedup vs baseline: 2.5943x; 1.5788x over previous
#include <cuda_runtime.h>
#include <cuda_bf16.h>
#include <cstdint>
#include <cstddef>

// Problem constants
constexpr int B_  = 4;
constexpr int S_  = 2048;
constexpr int H_  = 1024;
constexpr int NH_ = 16;
constexpr int HD_ = 64;
constexpr int M_  = B_ * S_;   // 8192 rows

constexpr float SCALE_Q = 0.18033688011112042f;  // 0.125 * log2(e)

// ---------------------------------------------------------------------------
// Scratch (device globals — no allocation allowed)
// ---------------------------------------------------------------------------
__device__ __nv_bfloat16 g_xhi[(size_t)M_ * H_];
__device__ __nv_bfloat16 g_xlo[(size_t)M_ * H_];
__device__ __nv_bfloat16 g_whi[4 * (size_t)H_ * H_];
__device__ __nv_bfloat16 g_wlo[4 * (size_t)H_ * H_];
__device__ __nv_bfloat16 g_qhi[(size_t)M_ * H_];   // [B*NH, S, HD]
__device__ __nv_bfloat16 g_qlo[(size_t)M_ * H_];
__device__ __nv_bfloat16 g_khi[(size_t)M_ * H_];
__device__ __nv_bfloat16 g_klo[(size_t)M_ * H_];
__device__ __nv_bfloat16 g_vhi[(size_t)M_ * H_];
__device__ __nv_bfloat16 g_vlo[(size_t)M_ * H_];
__device__ __nv_bfloat16 g_ahi[(size_t)M_ * H_];   // [B*S, H]
__device__ __nv_bfloat16 g_alo[(size_t)M_ * H_];

// ---------------------------------------------------------------------------
// Helpers (base sm_103 only: mma.sync / ldmatrix / cp.async — NO tcgen05)
// ---------------------------------------------------------------------------
__device__ __forceinline__ uint32_t smem_u32(const void* p) {
    uint32_t a;
    asm("{ .reg .u64 t; cvta.to.shared.u64 t, %1; cvt.u32.u64 %0, t; }"
        : "=r"(a) : "l"(p));
    return a;
}
__device__ __forceinline__ void cp_async16(uint32_t dst, const void* src) {
    asm volatile("cp.async.cg.shared.global [%0], [%1], 16;"
                 :: "r"(dst), "l"(src) : "memory");
}
#define CP_COMMIT() asm volatile("cp.async.commit_group;" ::: "memory")
#define CP_WAIT(n)  asm volatile("cp.async.wait_group %0;" :: "n"(n) : "memory")

__device__ __forceinline__ void ldmatrix_x4(uint32_t* r, uint32_t addr) {
    asm volatile("ldmatrix.sync.aligned.m8n8.x4.shared.b16 {%0,%1,%2,%3}, [%4];"
                 : "=r"(r[0]), "=r"(r[1]), "=r"(r[2]), "=r"(r[3]) : "r"(addr));
}
__device__ __forceinline__ void ldmatrix_x2(uint32_t* r, uint32_t addr) {
    asm volatile("ldmatrix.sync.aligned.m8n8.x2.shared.b16 {%0,%1}, [%2];"
                 : "=r"(r[0]), "=r"(r[1]) : "r"(addr));
}
__device__ __forceinline__ void ldmatrix_x2_trans(uint32_t* r, uint32_t addr) {
    asm volatile("ldmatrix.sync.aligned.m8n8.x2.trans.shared.b16 {%0,%1}, [%2];"
                 : "=r"(r[0]), "=r"(r[1]) : "r"(addr));
}
__device__ __forceinline__ void mma_bf16(float* c, const uint32_t* a,
                                         const uint32_t* b) {
    asm volatile(
        "mma.sync.aligned.m16n8k16.row.col.f32.bf16.bf16.f32 "
        "{%0,%1,%2,%3}, {%4,%5,%6,%7}, {%8,%9}, {%0,%1,%2,%3};"
        : "+f"(c[0]), "+f"(c[1]), "+f"(c[2]), "+f"(c[3])
        : "r"(a[0]), "r"(a[1]), "r"(a[2]), "r"(a[3]), "r"(b[0]), "r"(b[1]));
}
__device__ __forceinline__ float ex2f(float x) {
    float y;
    asm("ex2.approx.ftz.f32 %0, %1;" : "=f"(y) : "f"(x));
    return y;
}
__device__ __forceinline__ float trunc_bf(float x) {
    return __uint_as_float(__float_as_uint(x) & 0xFFFF0000u);
}
// pack hi16(a), hi16(b) -> u32 (low = a_hi16, high = b_hi16)
__device__ __forceinline__ uint32_t prmt7632(uint32_t a, uint32_t b) {
    uint32_t d;
    asm("prmt.b32 %0, %1, %2, 0x7632;" : "=r"(d) : "r"(a), "r"(b));
    return d;
}
// {hi half = cvt(h), lo half = cvt(l)}
__device__ __forceinline__ uint32_t bf16x2_rn(float h, float l) {
    uint32_t d;
    asm("cvt.rn.satfinite.bf16x2.f32 %0, %1, %2;" : "=r"(d) : "f"(h), "f"(l));
    return d;
}

// ---------------------------------------------------------------------------
// Split fp32 -> (bf16 hi, bf16 lo)
// ---------------------------------------------------------------------------
__global__ __launch_bounds__(256)
void split_kernel(const float* __restrict__ src,
                  __nv_bfloat16* __restrict__ hi,
                  __nv_bfloat16* __restrict__ lo, int n4)
{
    int i = blockIdx.x * blockDim.x + threadIdx.x;
    if (i >= n4) return;
    float4 v = reinterpret_cast<const float4*>(src)[i];
    float t0 = trunc_bf(v.x), t1 = trunc_bf(v.y), t2 = trunc_bf(v.z), t3 = trunc_bf(v.w);
    uint2 hu, lu;
    hu.x = prmt7632(__float_as_uint(v.x), __float_as_uint(v.y));
    hu.y = prmt7632(__float_as_uint(v.z), __float_as_uint(v.w));
    lu.x = bf16x2_rn(v.y - t1, v.x - t0);
    lu.y = bf16x2_rn(v.w - t3, v.z - t2);
    reinterpret_cast<uint2*>(hi)[i] = hu;
    reinterpret_cast<uint2*>(lo)[i] = lu;
}

// ---------------------------------------------------------------------------
// HMMA bf16x3 GEMM:  C = (A @ W^T + bias) * scale
// MODE 0: fp32 out [M, H].  MODE 1: bf16 hi/lo out scattered [B*NH, S, HD].
// ---------------------------------------------------------------------------
constexpr int BKK   = 32;
constexpr int RPAD  = 40;
constexpr int TILEB = 128 * RPAD * 2;
constexpr int BUFB  = 2 * TILEB;
constexpr int GEMM_SMEM = 2 * BUFB;

template <int MODE>
__global__ __launch_bounds__(256)
void gemm_mma(const __nv_bfloat16* __restrict__ Ahi,
              const __nv_bfloat16* __restrict__ Alo,
              const __nv_bfloat16* __restrict__ Whi,
              const __nv_bfloat16* __restrict__ Wlo,
              const float* __restrict__ bias, float* __restrict__ Cf,
              __nv_bfloat16* __restrict__ Chi, __nv_bfloat16* __restrict__ Clo,
              float scale)
{
    extern __shared__ char smem[];
    const uint32_t sb = smem_u32(smem);
    const int tid  = threadIdx.x;
    const int wid  = tid >> 5;
    const int lane = tid & 31;
    const int m0 = blockIdx.y * 128;
    const int n0 = blockIdx.x * 128;
    const int wm = (wid & 1) * 64;
    const int wn = (wid >> 1) * 32;

    float acc[4][4][4];
    #pragma unroll
    for (int mi = 0; mi < 4; mi++)
        #pragma unroll
        for (int ni = 0; ni < 4; ni++)
            #pragma unroll
            for (int r = 0; r < 4; r++) acc[mi][ni][r] = 0.f;

    const __nv_bfloat16* APASS[3] = {Ahi, Ahi, Alo};
    const __nv_bfloat16* BPASS[3] = {Whi, Wlo, Whi};
    constexpr int KCH = H_ / BKK;   // 32
    constexpr int NCH = 3 * KCH;    // 96

    auto issue_load = [&](int c) {
        const int pass = c / KCH, kc = c % KCH;
        const __nv_bfloat16* Ap = APASS[pass] + (size_t)m0 * H_ + kc * BKK;
        const __nv_bfloat16* Bp = BPASS[pass] + (size_t)n0 * H_ + kc * BKK;
        const uint32_t a_s = sb + (c & 1) * BUFB;
        const uint32_t b_s = a_s + TILEB;
        #pragma unroll
        for (int t = 0; t < 2; t++) {
            int u = tid + t * 256;
            int row = u >> 2, seg = u & 3;
            cp_async16(a_s + (row * RPAD + seg * 8) * 2,
                       Ap + (size_t)row * H_ + seg * 8);
            cp_async16(b_s + (row * RPAD + seg * 8) * 2,
                       Bp + (size_t)row * H_ + seg * 8);
        }
        CP_COMMIT();
    };

    issue_load(0);

    for (int c = 0; c < NCH; c++) {
        if (c + 1 < NCH) { issue_load(c + 1); CP_WAIT(1); }
        else             { CP_WAIT(0); }
        __syncthreads();

        const uint32_t a_s = sb + (c & 1) * BUFB;
        const uint32_t b_s = a_s + TILEB;

        #pragma unroll
        for (int ks = 0; ks < 2; ks++) {
            uint32_t a_frag[4][4], b_frag[4][2];
            #pragma unroll
            for (int mi = 0; mi < 4; mi++) {
                uint32_t addr = a_s +
                    ((wm + mi * 16 + (lane & 15)) * RPAD + ks * 16 + (lane >> 4) * 8) * 2;
                ldmatrix_x4(a_frag[mi], addr);
            }
            #pragma unroll
            for (int ni = 0; ni < 4; ni++) {
                int l = lane & 15;
                uint32_t addr = b_s +
                    ((wn + ni * 8 + (l & 7)) * RPAD + ks * 16 + (l >> 3) * 8) * 2;
                ldmatrix_x2(b_frag[ni], addr);
            }
            #pragma unroll
            for (int mi = 0; mi < 4; mi++)
                #pragma unroll
                for (int ni = 0; ni < 4; ni++)
                    mma_bf16(acc[mi][ni], a_frag[mi], b_frag[ni]);
        }
        __syncthreads();
    }

    const int frow = lane >> 2;
    const int fcol = (lane & 3) * 2;
    #pragma unroll
    for (int mi = 0; mi < 4; mi++) {
        #pragma unroll
        for (int ni = 0; ni < 4; ni++) {
            const int n = n0 + wn + ni * 8 + fcol;
            const float b0 = __ldg(&bias[n]);
            const float b1 = __ldg(&bias[n + 1]);
            #pragma unroll
            for (int half = 0; half < 2; half++) {
                const int m = m0 + wm + mi * 16 + frow + half * 8;
                float vx = (acc[mi][ni][half * 2 + 0] + b0) * scale;
                float vy = (acc[mi][ni][half * 2 + 1] + b1) * scale;
                if (MODE == 0) {
                    float2 val{vx, vy};
                    *reinterpret_cast<float2*>(&Cf[(size_t)m * H_ + n]) = val;
                } else {
                    const int b = m >> 11, s = m & 2047;
                    const int h = n >> 6, hd = n & 63;
                    size_t idx = (((size_t)(b * NH_ + h)) * S_ + s) * HD_ + hd;
                    uint32_t hi = prmt7632(__float_as_uint(vx), __float_as_uint(vy));
                    uint32_t lo = bf16x2_rn(vy - trunc_bf(vy), vx - trunc_bf(vx));
                    reinterpret_cast<uint32_t*>(Chi)[idx >> 1] = hi;
                    reinterpret_cast<uint32_t*>(Clo)[idx >> 1] = lo;
                }
            }
        }
    }
}

// ---------------------------------------------------------------------------
// Tensor-core flash attention (causal), bf16x3, base-2 softmax.
// 4 warps, BQ=64 queries, BKV=64 keys/iter, each warp m16 x n64.
// Q pre-scaled by 0.125*log2(e) in the projection epilogue.
// ---------------------------------------------------------------------------
constexpr int RP   = 72;                 // padded row (bf16 elems)
constexpr int TSZ  = 64 * RP * 2;        // 9216 B per 64x64 tile
constexpr int KVOFF = 2 * TSZ;           // Q hi/lo occupy the first two tiles
constexpr int ATTN_SMEM = 2 * TSZ + 2 * 4 * TSZ;   // 92160 B

__global__ __launch_bounds__(128)
void attn_mma(const __nv_bfloat16* __restrict__ qhi, const __nv_bfloat16* __restrict__ qlo,
              const __nv_bfloat16* __restrict__ khi, const __nv_bfloat16* __restrict__ klo,
              const __nv_bfloat16* __restrict__ vhi, const __nv_bfloat16* __restrict__ vlo,
              __nv_bfloat16* __restrict__ ahi, __nv_bfloat16* __restrict__ alo)
{
    extern __shared__ char smem[];
    const uint32_t sb = smem_u32(smem);
    const int tid  = threadIdx.x;
    const int wid  = tid >> 5;
    const int lane = tid & 31;
    const int qt = 31 - blockIdx.x;      // launch long CTAs first
    const int bh = blockIdx.y;
    const int q0 = qt * 64;
    const size_t boff = (size_t)bh * S_ * HD_;
    const int wm = wid * 16;

    auto cp_tile = [&](uint32_t dst, const __nv_bfloat16* src) {
        #pragma unroll
        for (int t = 0; t < 4; t++) {
            int u = tid + t * 128;
            int r = u >> 3, ch = u & 7;
            cp_async16(dst + (r * RP + ch * 8) * 2, src + (size_t)r * HD_ + ch * 8);
        }
    };
    // Q hi/lo
    cp_tile(sb,        qhi + boff + (size_t)q0 * HD_);
    cp_tile(sb + TSZ,  qlo + boff + (size_t)q0 * HD_);
    CP_COMMIT();

    auto issue = [&](int kt) {
        uint32_t kb = sb + KVOFF + (kt & 1) * 4 * TSZ;
        const size_t o = boff + (size_t)kt * 64 * HD_;
        cp_tile(kb,           khi + o);
        cp_tile(kb + TSZ,     klo + o);
        cp_tile(kb + 2 * TSZ, vhi + o);
        cp_tile(kb + 3 * TSZ, vlo + o);
        CP_COMMIT();
    };
    issue(0);

    CP_WAIT(1);              // Q in smem
    __syncthreads();

    // Q fragments (m16 x k64, hi & lo)
    uint32_t qh[4][4], ql[4][4];
    #pragma unroll
    for (int ks = 0; ks < 4; ks++) {
        uint32_t a = sb + ((wm + (lane & 15)) * RP + ks * 16 + (lane >> 4) * 8) * 2;
        ldmatrix_x4(qh[ks], a);
        ldmatrix_x4(ql[ks], a + TSZ);
    }

    float o[8][4];
    #pragma unroll
    for (int j = 0; j < 8; j++)
        #pragma unroll
        for (int r = 0; r < 4; r++) o[j][r] = 0.f;
    float m_i[2] = {-1e30f, -1e30f};
    float l_i[2] = {0.f, 0.f};

    for (int kt = 0; kt <= qt; kt++) {
        if (kt < qt) { issue(kt + 1); CP_WAIT(1); }
        else         { CP_WAIT(0); }
        __syncthreads();

        const uint32_t kb = sb + KVOFF + (kt & 1) * 4 * TSZ;

        // ---- S = Q @ K^T (bf16x3, base-2 units) ----
        float s[8][4];
        #pragma unroll
        for (int j = 0; j < 8; j++)
            #pragma unroll
            for (int r = 0; r < 4; r++) s[j][r] = 0.f;

        #pragma unroll
        for (int ks = 0; ks < 4; ks++) {
            #pragma unroll
            for (int j = 0; j < 8; j++) {
                uint32_t bh2[2], bl2[2];
                int l = lane & 15;
                uint32_t ka = kb + ((8 * j + (l & 7)) * RP + ks * 16 + (l >> 3) * 8) * 2;
                ldmatrix_x2(bh2, ka);
                ldmatrix_x2(bl2, ka + TSZ);
                mma_bf16(s[j], qh[ks], bh2);
                mma_bf16(s[j], ql[ks], bh2);
                mma_bf16(s[j], qh[ks], bl2);
            }
        }

        // ---- causal mask (diagonal tile only) ----
        if (kt == qt) {
            const int r0 = wm + (lane >> 2);
            #pragma unroll
            for (int j = 0; j < 8; j++) {
                const int kc = 8 * j + 2 * (lane & 3);
                if (kc     > r0)     s[j][0] = -1e30f;
                if (kc + 1 > r0)     s[j][1] = -1e30f;
                if (kc     > r0 + 8) s[j][2] = -1e30f;
                if (kc + 1 > r0 + 8) s[j][3] = -1e30f;
            }
        }

        // ---- online softmax (base 2) ----
        float mx0 = -1e30f, mx1 = -1e30f;
        #pragma unroll
        for (int j = 0; j < 8; j++) {
            mx0 = fmaxf(mx0, fmaxf(s[j][0], s[j][1]));
            mx1 = fmaxf(mx1, fmaxf(s[j][2], s[j][3]));
        }
        mx0 = fmaxf(mx0, __shfl_xor_sync(0xffffffffu, mx0, 1));
        mx0 = fmaxf(mx0, __shfl_xor_sync(0xffffffffu, mx0, 2));
        mx1 = fmaxf(mx1, __shfl_xor_sync(0xffffffffu, mx1, 1));
        mx1 = fmaxf(mx1, __shfl_xor_sync(0xffffffffu, mx1, 2));

        const float nm0 = fmaxf(m_i[0], mx0);
        const float nm1 = fmaxf(m_i[1], mx1);
        const float c0 = ex2f(m_i[0] - nm0);
        const float c1 = ex2f(m_i[1] - nm1);
        m_i[0] = nm0; m_i[1] = nm1;

        float rs0 = 0.f, rs1 = 0.f;
        #pragma unroll
        for (int j = 0; j < 8; j++) {
            s[j][0] = ex2f(s[j][0] - nm0);
            s[j][1] = ex2f(s[j][1] - nm0);
            s[j][2] = ex2f(s[j][2] - nm1);
            s[j][3] = ex2f(s[j][3] - nm1);
            rs0 += s[j][0] + s[j][1];
            rs1 += s[j][2] + s[j][3];
        }
        rs0 += __shfl_xor_sync(0xffffffffu, rs0, 1);
        rs0 += __shfl_xor_sync(0xffffffffu, rs0, 2);
        rs1 += __shfl_xor_sync(0xffffffffu, rs1, 1);
        rs1 += __shfl_xor_sync(0xffffffffu, rs1, 2);
        l_i[0] = l_i[0] * c0 + rs0;
        l_i[1] = l_i[1] * c1 + rs1;
        #pragma unroll
        for (int j = 0; j < 8; j++) {
            o[j][0] *= c0; o[j][1] *= c0;
            o[j][2] *= c1; o[j][3] *= c1;
        }

        // ---- pack P into A-fragments (hi trunc + exact lo) ----
        uint32_t ph[4][4], pl[4][4];
        #pragma unroll
        for (int k2 = 0; k2 < 4; k2++) {
            #pragma unroll
            for (int half = 0; half < 2; half++) {
                const int j = 2 * k2 + half;
                ph[k2][half * 2 + 0] = prmt7632(__float_as_uint(s[j][0]),
                                                __float_as_uint(s[j][1]));
                ph[k2][half * 2 + 1] = prmt7632(__float_as_uint(s[j][2]),
                                                __float_as_uint(s[j][3]));
                pl[k2][half * 2 + 0] = bf16x2_rn(s[j][1] - trunc_bf(s[j][1]),
                                                 s[j][0] - trunc_bf(s[j][0]));
                pl[k2][half * 2 + 1] = bf16x2_rn(s[j][3] - trunc_bf(s[j][3]),
                                                 s[j][2] - trunc_bf(s[j][2]));
            }
        }
        // NOTE: A-frag needs [a0,a1] = k0..7 (rows r, r+8), [a2,a3] = k8..15.
        // ph[k2][0]=tile(2k2) rows(r,?)... mapping: a0=(r,k0-7)=tile2k2 c0c1,
        // a1=(r+8,k0-7)=tile2k2 c2c3, a2=(r,k8-15)=tile2k2+1 c0c1, a3=c2c3. OK:
        // half=0 wrote [0]=t2k2(c01), [1]=t2k2(c23); half=1 wrote [2],[3]. Correct.

        // ---- O += P @ V (bf16x3) ----
        const uint32_t vb = kb + 2 * TSZ;
        #pragma unroll
        for (int k2 = 0; k2 < 4; k2++) {
            #pragma unroll
            for (int j = 0; j < 8; j++) {
                uint32_t vh2[2], vl2[2];
                uint32_t va = vb + ((k2 * 16 + (lane & 15)) * RP + 8 * j) * 2;
                ldmatrix_x2_trans(vh2, va);
                ldmatrix_x2_trans(vl2, va + TSZ);
                mma_bf16(o[j], ph[k2], vh2);
                mma_bf16(o[j], pl[k2], vh2);
                mma_bf16(o[j], ph[k2], vl2);
            }
        }
        __syncthreads();
    }

    // ---- epilogue: normalize, write bf16 hi/lo to [B,S,H] ----
    const float inv0 = 1.f / l_i[0];
    const float inv1 = 1.f / l_i[1];
    const int b = bh >> 4, h = bh & 15;
    const int r0 = q0 + wm + (lane >> 2);
    const size_t base0 = ((size_t)(b * S_) + r0) * H_ + h * 64;
    const size_t base1 = base0 + (size_t)8 * H_;
    #pragma unroll
    for (int j = 0; j < 8; j++) {
        const int c = 8 * j + 2 * (lane & 3);
        float f00 = o[j][0] * inv0, f01 = o[j][1] * inv0;
        float f10 = o[j][2] * inv1, f11 = o[j][3] * inv1;
        uint32_t hi0 = prmt7632(__float_as_uint(f00), __float_as_uint(f01));
        uint32_t lo0 = bf16x2_rn(f01 - trunc_bf(f01), f00 - trunc_bf(f00));
        uint32_t hi1 = prmt7632(__float_as_uint(f10), __float_as_uint(f11));
        uint32_t lo1 = bf16x2_rn(f11 - trunc_bf(f11), f10 - trunc_bf(f10));
        reinterpret_cast<uint32_t*>(ahi)[(base0 + c) >> 1] = hi0;
        reinterpret_cast<uint32_t*>(alo)[(base0 + c) >> 1] = lo0;
        reinterpret_cast<uint32_t*>(ahi)[(base1 + c) >> 1] = hi1;
        reinterpret_cast<uint32_t*>(alo)[(base1 + c) >> 1] = lo1;
    }
}

// ---------------------------------------------------------------------------
// Launch
// ---------------------------------------------------------------------------
extern "C" void kernel_launch(void* const* d_in, const int* in_sizes, int n_in,
                              void* d_out, int out_size)
{
    const float* x  = (const float*)d_in[0];
    const float* Wq = (const float*)d_in[1];
    const float* bq = (const float*)d_in[2];
    const float* Wk = (const float*)d_in[3];
    const float* bk = (const float*)d_in[4];
    const float* Wv = (const float*)d_in[5];
    const float* bv = (const float*)d_in[6];
    const float* Wo = (const float*)d_in[7];
    const float* bo = (const float*)d_in[8];
    float* out = (float*)d_out;

    __nv_bfloat16 *xhi, *xlo, *whi, *wlo;
    __nv_bfloat16 *q_hi, *q_lo, *k_hi, *k_lo, *v_hi, *v_lo, *a_hi, *a_lo;
    cudaGetSymbolAddress((void**)&xhi, g_xhi);
    cudaGetSymbolAddress((void**)&xlo, g_xlo);
    cudaGetSymbolAddress((void**)&whi, g_whi);
    cudaGetSymbolAddress((void**)&wlo, g_wlo);
    cudaGetSymbolAddress((void**)&q_hi, g_qhi);
    cudaGetSymbolAddress((void**)&q_lo, g_qlo);
    cudaGetSymbolAddress((void**)&k_hi, g_khi);
    cudaGetSymbolAddress((void**)&k_lo, g_klo);
    cudaGetSymbolAddress((void**)&v_hi, g_vhi);
    cudaGetSymbolAddress((void**)&v_lo, g_vlo);
    cudaGetSymbolAddress((void**)&a_hi, g_ahi);
    cudaGetSymbolAddress((void**)&a_lo, g_alo);

    cudaFuncSetAttribute(gemm_mma<0>,
                         cudaFuncAttributeMaxDynamicSharedMemorySize, GEMM_SMEM);
    cudaFuncSetAttribute(gemm_mma<1>,
                         cudaFuncAttributeMaxDynamicSharedMemorySize, GEMM_SMEM);
    cudaFuncSetAttribute(attn_mma,
                         cudaFuncAttributeMaxDynamicSharedMemorySize, ATTN_SMEM);

    const size_t WN = (size_t)H_ * H_;

    {
        int n4 = (M_ * H_) / 4;
        split_kernel<<<(n4 + 255) / 256, 256>>>(x, xhi, xlo, n4);
        int w4 = (H_ * H_) / 4;
        split_kernel<<<(w4 + 255) / 256, 256>>>(Wq, whi + 0 * WN, wlo + 0 * WN, w4);
        split_kernel<<<(w4 + 255) / 256, 256>>>(Wk, whi + 1 * WN, wlo + 1 * WN, w4);
        split_kernel<<<(w4 + 255) / 256, 256>>>(Wv, whi + 2 * WN, wlo + 2 * WN, w4);
        split_kernel<<<(w4 + 255) / 256, 256>>>(Wo, whi + 3 * WN, wlo + 3 * WN, w4);
    }

    dim3 ggrid(H_ / 128, M_ / 128);   // (8, 64)
    gemm_mma<1><<<ggrid, 256, GEMM_SMEM>>>(xhi, xlo, whi + 0 * WN, wlo + 0 * WN,
                                           bq, nullptr, q_hi, q_lo, SCALE_Q);
    gemm_mma<1><<<ggrid, 256, GEMM_SMEM>>>(xhi, xlo, whi + 1 * WN, wlo + 1 * WN,
                                           bk, nullptr, k_hi, k_lo, 1.0f);
    gemm_mma<1><<<ggrid, 256, GEMM_SMEM>>>(xhi, xlo, whi + 2 * WN, wlo + 2 * WN,
                                           bv, nullptr, v_hi, v_lo, 1.0f);

    dim3 agrid(S_ / 64, B_ * NH_);    // (32, 64)
    attn_mma<<<agrid, 128, ATTN_SMEM>>>(q_hi, q_lo, k_hi, k_lo, v_hi, v_lo,
                                        a_hi, a_lo);

    gemm_mma<0><<<ggrid, 256, GEMM_SMEM>>>(a_hi, a_lo, whi + 3 * WN, wlo + 3 * WN,
                                           bo, out, nullptr, nullptr, 1.0f);
}